// round 2
// baseline (speedup 1.0000x reference)
#include <cuda_runtime.h>
#include <cstdint>

// Problem constants (fixed by the dataset)
#define NMAX 50000
#define RK 300

// Scratch (allocation-free rule: __device__ globals)
__device__ float g_h[NMAX * 64];
__device__ float g_agg[NMAX * 64];
__device__ float g_fw1r[RK * 64];
__device__ float g_fw2r[64 * 64];
__device__ int g_is64;

__device__ __forceinline__ float sspf(float x) {
    float t = __expf(-fabsf(x));
    return fmaxf(x, 0.f) + __logf(1.f + t) - 0.69314718055994531f;
}

__device__ __forceinline__ uint32_t cvt_tf32(float x) {
    uint32_t r;
    asm("cvt.rna.tf32.f32 %0, %1;" : "=r"(r) : "f"(x));
    return r;
}

__device__ __forceinline__ void mma_tf32(float d[4], uint32_t a0, uint32_t a1,
                                         uint32_t a2, uint32_t a3,
                                         uint32_t b0, uint32_t b1) {
    asm volatile(
        "mma.sync.aligned.m16n8k8.row.col.f32.tf32.tf32.f32 "
        "{%0,%1,%2,%3}, {%4,%5,%6,%7}, {%8,%9}, {%0,%1,%2,%3};"
        : "+f"(d[0]), "+f"(d[1]), "+f"(d[2]), "+f"(d[3])
        : "r"(a0), "r"(a1), "r"(a2), "r"(a3), "r"(b0), "r"(b1));
}

__device__ __forceinline__ void cp16(uint32_t saddr, const void* g, int sz) {
    asm volatile("cp.async.cg.shared.global [%0], [%1], 16, %2;"
                 :: "r"(saddr), "l"(g), "r"(sz));
}
__device__ __forceinline__ void cp_commit() { asm volatile("cp.async.commit_group;"); }
__device__ __forceinline__ void cp_wait1()  { asm volatile("cp.async.wait_group 1;"); }
__device__ __forceinline__ void cp_wait0()  { asm volatile("cp.async.wait_group 0;"); }

// ---------------------------------------------------------------------------
// Detect whether edge_index buffer is int64 or int32.
// If int64 (values < 2^31), every odd 32-bit word of the first 64 pairs is 0.
// ---------------------------------------------------------------------------
__global__ void detect_idx_kernel(const int* __restrict__ ei32) {
    if (threadIdx.x == 0 && blockIdx.x == 0) {
        int ornz = 0;
#pragma unroll
        for (int i = 0; i < 64; ++i) ornz |= ei32[2 * i + 1];
        g_is64 = (ornz == 0) ? 1 : 0;
    }
}

// ---------------------------------------------------------------------------
// Kernel P: round fw1/fw2 to tf32 once (unbiased rounding for mma inputs)
// ---------------------------------------------------------------------------
__global__ void prep_weights_kernel(const float* __restrict__ fw1,
                                    const float* __restrict__ fw2) {
    int i = blockIdx.x * blockDim.x + threadIdx.x;
    if (i < RK * 64) g_fw1r[i] = __uint_as_float(cvt_tf32(fw1[i]));
    if (i < 64 * 64) g_fw2r[i] = __uint_as_float(cvt_tf32(fw2[i]));
}

__global__ void zero_agg_kernel(int total4) {
    int i = blockIdx.x * blockDim.x + threadIdx.x;
    if (i < total4) ((float4*)g_agg)[i] = make_float4(0.f, 0.f, 0.f, 0.f);
}

// ---------------------------------------------------------------------------
// Kernel A: h = node_feature @ l1w + l1b
// ---------------------------------------------------------------------------
__global__ void node_pre_kernel(const float* __restrict__ x, const float* __restrict__ W,
                                const float* __restrict__ b, int N) {
    __shared__ float Ws[64 * 65];
    __shared__ float bs[64];
    __shared__ float xs[4][68];
    int tid = threadIdx.x;
    for (int i = tid; i < 4096; i += 256) Ws[(i >> 6) * 65 + (i & 63)] = W[i];
    if (tid < 64) bs[tid] = b[tid];
    int j = tid & 63, g = tid >> 6;
    int n0 = blockIdx.x * 64;
    for (int it = 0; it < 16; ++it) {
        int node = n0 + it * 4 + g;
        __syncthreads();
        xs[g][j] = (node < N) ? x[(long)node * 64 + j] : 0.f;
        __syncthreads();
        float acc = bs[j];
#pragma unroll
        for (int k = 0; k < 64; k += 4) {
            float4 xv = *(const float4*)&xs[g][k];
            acc += xv.x * Ws[(k + 0) * 65 + j];
            acc += xv.y * Ws[(k + 1) * 65 + j];
            acc += xv.z * Ws[(k + 2) * 65 + j];
            acc += xv.w * Ws[(k + 3) * 65 + j];
        }
        if (node < N) g_h[(long)node * 64 + j] = acc;
    }
}

// ---------------------------------------------------------------------------
// Kernel B: fused per-edge filter network + cfconv gather/scatter
//   w1 = ssp(rbf @ fw1 + fb1); w2 = ssp(w1 @ fw2 + fb2)
//   msg = h[src] * w2 * (1 + cos(pi*dist/cutoff)); atomicAdd agg[dst]
// Tile: 128 edges/CTA, 256 threads (8 warps, each 16 rows x 64 cols), tf32 mma.
// ---------------------------------------------------------------------------
#define SA_STRIDE 36
#define SW_STRIDE 72
#define SC_STRIDE 68
#define OFF_A  0                     // 2 * 128 * 36 = 9216
#define OFF_W1 9216                  // 2 * 32 * 72  = 4608
#define OFF_W2 13824                 // 64 * 72      = 4608
#define OFF_C  18432                 // 128 * 68     = 8704
#define OFF_B1 27136
#define OFF_B2 27200
#define SMEM_FLOATS 27264

__global__ void __launch_bounds__(256, 2)
edge_kernel(const void* __restrict__ ei, const float* __restrict__ rbf,
            const float* __restrict__ dist, const float* __restrict__ cutoff,
            const float* __restrict__ fb1, const float* __restrict__ fb2, int E) {
    extern __shared__ float sm[];
    uint32_t sbase = (uint32_t)__cvta_generic_to_shared(sm);
    int tid = threadIdx.x;
    int lane = tid & 31, warp = tid >> 5;
    long tile = (long)blockIdx.x * 128;

    // stage rounded fw2 and biases (plain loads; covered by first barrier)
    for (int i = tid; i < 4096; i += 256)
        sm[OFF_W2 + (i >> 6) * SW_STRIDE + (i & 63)] = g_fw2r[i];
    if (tid < 64) { sm[OFF_B1 + tid] = fb1[tid]; sm[OFF_B2 + tid] = fb2[tid]; }

    auto load_chunk = [&](int c, int buf) {
        int k0 = c * 32;
        // A tile slab: 128 rows x 32 cols -> 1024 x 16B tasks
#pragma unroll
        for (int i = 0; i < 4; ++i) {
            int task = tid + i * 256;
            int row = task >> 3, q = task & 7;
            long e = tile + row;
            uint32_t dst = sbase + (OFF_A + buf * 128 * SA_STRIDE + row * SA_STRIDE + q * 4) * 4;
            bool ok = (e < (long)E) && (k0 + q * 4 + 4 <= RK);
            const float* src = ok ? (rbf + e * (long)RK + k0 + q * 4) : rbf;
            cp16(dst, src, ok ? 16 : 0);
        }
        // fw1 slab: 32 rows x 64 cols -> 512 x 16B tasks
#pragma unroll
        for (int i = 0; i < 2; ++i) {
            int task = tid + i * 256;
            int r = task >> 4, q = task & 15;
            int kr = k0 + r;
            uint32_t dst = sbase + (OFF_W1 + buf * 32 * SW_STRIDE + r * SW_STRIDE + q * 4) * 4;
            bool ok = (kr < RK);
            const float* src = ok ? (g_fw1r + (long)kr * 64 + q * 4) : g_fw1r;
            cp16(dst, src, ok ? 16 : 0);
        }
    };

    float acc[8][4];
#pragma unroll
    for (int t = 0; t < 8; ++t)
#pragma unroll
        for (int jj = 0; jj < 4; ++jj) acc[t][jj] = 0.f;

    load_chunk(0, 0);
    cp_commit();

    int rw = warp * 16;
    int g4 = lane >> 2, t4 = lane & 3;

    // ---- GEMM1: K padded 300 -> 320, 10 chunks of 32, double-buffered ----
    for (int c = 0; c < 10; ++c) {
        int buf = c & 1;
        if (c < 9) { load_chunk(c + 1, buf ^ 1); cp_commit(); cp_wait1(); }
        else cp_wait0();
        __syncthreads();
        const float* A = sm + OFF_A + buf * 128 * SA_STRIDE;
        const float* B = sm + OFF_W1 + buf * 32 * SW_STRIDE;
#pragma unroll
        for (int s = 0; s < 4; ++s) {
            int col = 8 * s + t4;
            uint32_t a0 = cvt_tf32(A[(rw + g4) * SA_STRIDE + col]);
            uint32_t a1 = cvt_tf32(A[(rw + g4 + 8) * SA_STRIDE + col]);
            uint32_t a2 = cvt_tf32(A[(rw + g4) * SA_STRIDE + col + 4]);
            uint32_t a3 = cvt_tf32(A[(rw + g4 + 8) * SA_STRIDE + col + 4]);
#pragma unroll
            for (int t = 0; t < 8; ++t) {
                uint32_t b0 = __float_as_uint(B[col * SW_STRIDE + 8 * t + g4]);
                uint32_t b1 = __float_as_uint(B[(col + 4) * SW_STRIDE + 8 * t + g4]);
                mma_tf32(acc[t], a0, a1, a2, a3, b0, b1);
            }
        }
        __syncthreads();
    }

    // ---- bias + ssp -> stage C1 in smem (warp-local rows only) ----
#pragma unroll
    for (int t = 0; t < 8; ++t) {
        int cb = 8 * t + 2 * t4;
        float b0v = sm[OFF_B1 + cb], b1v = sm[OFF_B1 + cb + 1];
        float2 v0 = make_float2(sspf(acc[t][0] + b0v), sspf(acc[t][1] + b1v));
        float2 v1 = make_float2(sspf(acc[t][2] + b0v), sspf(acc[t][3] + b1v));
        *(float2*)&sm[OFF_C + (rw + g4) * SC_STRIDE + cb] = v0;
        *(float2*)&sm[OFF_C + (rw + g4 + 8) * SC_STRIDE + cb] = v1;
    }
    __syncwarp();

    // ---- GEMM2: C1[128,64] @ fw2[64,64] ----
    float acc2[8][4];
#pragma unroll
    for (int t = 0; t < 8; ++t)
#pragma unroll
        for (int jj = 0; jj < 4; ++jj) acc2[t][jj] = 0.f;

#pragma unroll
    for (int s = 0; s < 8; ++s) {
        int col = 8 * s + t4;
        uint32_t a0 = cvt_tf32(sm[OFF_C + (rw + g4) * SC_STRIDE + col]);
        uint32_t a1 = cvt_tf32(sm[OFF_C + (rw + g4 + 8) * SC_STRIDE + col]);
        uint32_t a2 = cvt_tf32(sm[OFF_C + (rw + g4) * SC_STRIDE + col + 4]);
        uint32_t a3 = cvt_tf32(sm[OFF_C + (rw + g4 + 8) * SC_STRIDE + col + 4]);
#pragma unroll
        for (int t = 0; t < 8; ++t) {
            uint32_t b0 = __float_as_uint(sm[OFF_W2 + col * SW_STRIDE + 8 * t + g4]);
            uint32_t b1 = __float_as_uint(sm[OFF_W2 + (col + 4) * SW_STRIDE + 8 * t + g4]);
            mma_tf32(acc2[t], a0, a1, a2, a3, b0, b1);
        }
    }
    __syncwarp();

    // ---- bias + ssp -> stage w2 in smem ----
#pragma unroll
    for (int t = 0; t < 8; ++t) {
        int cb = 8 * t + 2 * t4;
        float b0v = sm[OFF_B2 + cb], b1v = sm[OFF_B2 + cb + 1];
        float2 v0 = make_float2(sspf(acc2[t][0] + b0v), sspf(acc2[t][1] + b1v));
        float2 v1 = make_float2(sspf(acc2[t][2] + b0v), sspf(acc2[t][3] + b1v));
        *(float2*)&sm[OFF_C + (rw + g4) * SC_STRIDE + cb] = v0;
        *(float2*)&sm[OFF_C + (rw + g4 + 8) * SC_STRIDE + cb] = v1;
    }
    __syncthreads();

    // ---- epilogue: cutoff * h[src] gather, float4 atomic scatter to agg[dst] ----
    int el = tid >> 1, half = tid & 1;
    long e = tile + el;
    if (e < (long)E) {
        long long dstn, srcn;
        if (g_is64) {
            const long long* p = (const long long*)ei;
            dstn = p[e]; srcn = p[(long)E + e];
        } else {
            const int* p = (const int*)ei;
            dstn = p[e]; srcn = p[(long)E + e];
        }
        // clamp: IMA-proof even under a dtype surprise (wrong answer > crash)
        dstn = dstn < 0 ? 0 : (dstn >= NMAX ? NMAX - 1 : dstn);
        srcn = srcn < 0 ? 0 : (srcn >= NMAX ? NMAX - 1 : srcn);
        float cf = *cutoff;
        float f = 1.f + __cosf(3.14159265f * dist[e] / cf);
        const float* hrow = g_h + (long)srcn * 64 + half * 32;
        float* arow = g_agg + (long)dstn * 64 + half * 32;
        const float* wrow = sm + OFF_C + el * SC_STRIDE + half * 32;
#pragma unroll
        for (int j = 0; j < 8; ++j) {
            float4 w = *(const float4*)(wrow + 4 * j);
            float4 h4 = *(const float4*)(hrow + 4 * j);
            float4 m = make_float4(w.x * h4.x * f, w.y * h4.y * f,
                                   w.z * h4.z * f, w.w * h4.w * f);
            atomicAdd((float4*)(arow + 4 * j), m);
        }
    }
}

// ---------------------------------------------------------------------------
// Kernel C: out = ssp(agg @ l2w + l2b) @ l3w + l3b + x0
// ---------------------------------------------------------------------------
__global__ void node_post_kernel(const float* __restrict__ x0, const float* __restrict__ W2,
                                 const float* __restrict__ b2, const float* __restrict__ W3,
                                 const float* __restrict__ b3, float* __restrict__ out, int N) {
    __shared__ float W2s[64 * 65], W3s[64 * 65];
    __shared__ float b2s[64], b3s[64];
    __shared__ float xs[4][68], ts[4][68];
    int tid = threadIdx.x;
    for (int i = tid; i < 4096; i += 256) {
        W2s[(i >> 6) * 65 + (i & 63)] = W2[i];
        W3s[(i >> 6) * 65 + (i & 63)] = W3[i];
    }
    if (tid < 64) { b2s[tid] = b2[tid]; b3s[tid] = b3[tid]; }
    int j = tid & 63, g = tid >> 6;
    int n0 = blockIdx.x * 64;
    for (int it = 0; it < 16; ++it) {
        int node = n0 + it * 4 + g;
        __syncthreads();
        xs[g][j] = (node < N) ? g_agg[(long)node * 64 + j] : 0.f;
        __syncthreads();
        float acc = b2s[j];
#pragma unroll
        for (int k = 0; k < 64; k += 4) {
            float4 xv = *(const float4*)&xs[g][k];
            acc += xv.x * W2s[(k + 0) * 65 + j];
            acc += xv.y * W2s[(k + 1) * 65 + j];
            acc += xv.z * W2s[(k + 2) * 65 + j];
            acc += xv.w * W2s[(k + 3) * 65 + j];
        }
        ts[g][j] = sspf(acc);
        __syncthreads();
        float acc2 = b3s[j];
#pragma unroll
        for (int k = 0; k < 64; k += 4) {
            float4 tv = *(const float4*)&ts[g][k];
            acc2 += tv.x * W3s[(k + 0) * 65 + j];
            acc2 += tv.y * W3s[(k + 1) * 65 + j];
            acc2 += tv.z * W3s[(k + 2) * 65 + j];
            acc2 += tv.w * W3s[(k + 3) * 65 + j];
        }
        if (node < N) out[(long)node * 64 + j] = acc2 + x0[(long)node * 64 + j];
    }
}

// ---------------------------------------------------------------------------
extern "C" void kernel_launch(void* const* d_in, const int* in_sizes, int n_in,
                              void* d_out, int out_size) {
    const void* ei       = d_in[0];
    const float* x       = (const float*)d_in[1];
    const float* rbf     = (const float*)d_in[2];
    const float* dist    = (const float*)d_in[3];
    const float* cutoff  = (const float*)d_in[4];
    const float* fw1     = (const float*)d_in[5];
    const float* fb1     = (const float*)d_in[6];
    const float* fw2     = (const float*)d_in[7];
    const float* fb2     = (const float*)d_in[8];
    const float* l1w     = (const float*)d_in[9];
    const float* l1b     = (const float*)d_in[10];
    const float* l2w     = (const float*)d_in[11];
    const float* l2b     = (const float*)d_in[12];
    const float* l3w     = (const float*)d_in[13];
    const float* l3b     = (const float*)d_in[14];

    int E = in_sizes[0] / 2;
    int N = in_sizes[1] / 64;

    cudaFuncSetAttribute(edge_kernel, cudaFuncAttributeMaxDynamicSharedMemorySize,
                         SMEM_FLOATS * 4);

    detect_idx_kernel<<<1, 32>>>((const int*)ei);
    prep_weights_kernel<<<(RK * 64 + 255) / 256, 256>>>(fw1, fw2);
    zero_agg_kernel<<<(N * 16 + 255) / 256, 256>>>(N * 16);
    node_pre_kernel<<<(N + 63) / 64, 256>>>(x, l1w, l1b, N);
    edge_kernel<<<(E + 127) / 128, 256, SMEM_FLOATS * 4>>>(ei, rbf, dist, cutoff,
                                                           fb1, fb2, E);
    node_post_kernel<<<(N + 63) / 64, 256>>>(x, l2w, l2b, l3w, l3b, (float*)d_out, N);
}